// round 3
// baseline (speedup 1.0000x reference)
#include <cuda_runtime.h>
#include <cstdint>
#include <math.h>

// ============================================================================
// VideokMaXTransformerDecoder — round 2 (identical to R1; resubmitted to
// bisect broker-level container failure vs kernel fault — see analysis)
// All fp32 (exact vs reference), f32x2 packed FMA for 2x fp32 throughput.
// 9 kernel launches, sequential on default stream, graph-capturable,
// allocation-free (scratch in __device__ globals).
// ============================================================================

#define DEV __device__ __forceinline__
using u64 = unsigned long long;

DEV u64 ffma2(u64 a, u64 b, u64 c) {
    u64 d; asm("fma.rn.f32x2 %0,%1,%2,%3;" : "=l"(d) : "l"(a), "l"(b), "l"(c)); return d;
}
DEV u64 fmul2(u64 a, u64 b) {
    u64 d; asm("mul.rn.f32x2 %0,%1,%2;" : "=l"(d) : "l"(a), "l"(b)); return d;
}
DEV u64 pack2(float x, float y) {
    u64 d; asm("mov.b64 %0,{%1,%2};" : "=l"(d) : "f"(x), "f"(y)); return d;
}
DEV float2 unpack2(u64 v) {
    float2 f; asm("mov.b64 {%0,%1},%2;" : "=f"(f.x), "=f"(f.y) : "l"(v)); return f;
}
DEV float gelu_f(float x) { return 0.5f * x * (1.0f + erff(x * 0.7071067811865476f)); }

// ---------------------------------------------------------------------------
// Shapes
// ---------------------------------------------------------------------------
static constexpr int NB   = 8;      // batch
static constexpr int CP   = 2048;   // pixel channels
static constexpr int HW   = 4096;   // 64*64
static constexpr int CQ   = 256;
static constexpr int LQ   = 128;
static constexpr int NH   = 8;
static constexpr int DK   = 16;     // KD/NH
static constexpr int DV   = 32;     // VD/NH
static constexpr int MT   = 4224;   // L + HW
static constexpr int NQ   = 1024;   // NB * LQ  (query-side flattened columns)
static constexpr int MSPLIT = 4;    // attention m-splits across blocks
static constexpr int MSLAB  = MT / MSPLIT; // 1056

// ---------------------------------------------------------------------------
// Scratch (device globals; no allocation allowed)
// ---------------------------------------------------------------------------
__device__ float g_pixel_space[(size_t)NB * 256 * HW];          // [b][c][hw]
__device__ float g_kbuf[(size_t)NB * NH * DK * MT];             // [b*NH+h][d][m]
__device__ float g_vbuf[(size_t)NB * NH * DV * MT];             // [b*NH+h][d][m]
__device__ float g_qbuf[(size_t)NB * NH * DK * LQ];             // [b*NH+h][d][l]
__device__ float g_qs  [(size_t)256  * NQ];                      // [c][b*128+l]
__device__ float g_ret [(size_t)256  * NQ];
__device__ float g_qf  [(size_t)256  * NQ];
__device__ float g_ffn [(size_t)2048 * NQ];
__device__ float g_part_mx [64 * MSPLIT * LQ];
__device__ float g_part_sum[64 * MSPLIT * LQ];
__device__ float g_part_acc[(size_t)64 * MSPLIT * DV * LQ];     // [bh*4+ms][d][l]

// ---------------------------------------------------------------------------
// Generic tiled GEMM  C[m,n] = sum_k A[m,k] * B[k,n]   (+ fused epilogues)
// ---------------------------------------------------------------------------
enum { M_PIX1 = 0, M_PKV = 1, M_Q1 = 2, M_QKV = 3, M_C3 = 4, M_F1 = 5, M_F2 = 6 };

template <int BM, int BN, int BK, int TM, int TN, int MODE>
__global__ void __launch_bounds__((BM / TM) * (BN / TN))
gemm_k(const float* __restrict__ A,
       const float* __restrict__ B,
       const float* __restrict__ scale,
       const float* __restrict__ bias,
       const float* __restrict__ extra,
       float* __restrict__ C,
       int K)
{
    constexpr int THREADS = (BM / TM) * (BN / TN);
    constexpr int PAD = 4;
    constexpr int AE = BM * BK / THREADS;
    constexpr int BE = BK * BN / THREADS;
    constexpr int LDB = (MODE == M_PIX1 || MODE == M_PKV) ? HW : NQ;

    __shared__ float As[2][BK][BM + PAD];
    __shared__ float Bs[2][BK][BN];

    const int tid = threadIdx.x;
    const int bz  = blockIdx.z;
    const int m0  = blockIdx.x * BM;
    const int n0  = blockIdx.y * BN;
    const int tx  = tid % (BN / TN);
    const int ty  = tid / (BN / TN);

    const float* Bb;
    if constexpr (MODE == M_PIX1)      Bb = B + (size_t)bz * CP * HW;
    else if constexpr (MODE == M_PKV)  Bb = g_pixel_space + (size_t)bz * 256 * HW;
    else if constexpr (MODE == M_QKV)  Bb = g_qs;
    else if constexpr (MODE == M_C3)   Bb = g_ret;
    else if constexpr (MODE == M_F1)   Bb = g_qf;
    else if constexpr (MODE == M_F2)   Bb = g_ffn;
    else                               Bb = B;   // M_Q1: special indexing

    float areg[AE], breg[BE];

    auto gloadA = [&](int k0) {
#pragma unroll
        for (int r = 0; r < AE; r++) {
            int e = r * THREADS + tid;
            int i = e / BK, kk = e % BK;
            areg[r] = A[(size_t)(m0 + i) * K + k0 + kk];
        }
    };
    auto gloadB = [&](int k0) {
#pragma unroll
        for (int r = 0; r < BE; r++) {
            int e = r * THREADS + tid;
            int kk = e / BN, j = e % BN;
            float v;
            if constexpr (MODE == M_PIX1) {
                v = gelu_f(Bb[(size_t)(k0 + kk) * LDB + n0 + j]);
            } else if constexpr (MODE == M_Q1) {
                int jj = n0 + j;
                v = Bb[((jj >> 7) << 15) + (k0 + kk) * LQ + (jj & 127)];
            } else {
                v = Bb[(size_t)(k0 + kk) * LDB + n0 + j];
            }
            breg[r] = v;
        }
    };
    auto sstore = [&](int buf) {
#pragma unroll
        for (int r = 0; r < AE; r++) {
            int e = r * THREADS + tid;
            int i = e / BK, kk = e % BK;
            As[buf][kk][i] = areg[r];
        }
#pragma unroll
        for (int r = 0; r < BE; r++) {
            int e = r * THREADS + tid;
            int kk = e / BN, j = e % BN;
            Bs[buf][kk][j] = breg[r];
        }
    };

    u64 acc[TM][TN / 2];
#pragma unroll
    for (int i = 0; i < TM; i++)
#pragma unroll
        for (int jp = 0; jp < TN / 2; jp++) acc[i][jp] = 0ull;

    gloadA(0); gloadB(0); sstore(0);
    __syncthreads();

    const int nk = K / BK;
    for (int t = 0; t < nk; t++) {
        const int cur = t & 1;
        if (t + 1 < nk) { gloadA((t + 1) * BK); gloadB((t + 1) * BK); }
#pragma unroll
        for (int kk = 0; kk < BK; kk++) {
            u64 a2[TM];
#pragma unroll
            for (int i = 0; i < TM; i += 4) {
                float4 av = *(const float4*)&As[cur][kk][ty * TM + i];
                a2[i + 0] = pack2(av.x, av.x);
                a2[i + 1] = pack2(av.y, av.y);
                a2[i + 2] = pack2(av.z, av.z);
                a2[i + 3] = pack2(av.w, av.w);
            }
            u64 b2[TN / 2];
#pragma unroll
            for (int jp = 0; jp < TN / 2; jp++)
                b2[jp] = *(const u64*)&Bs[cur][kk][tx * TN + 2 * jp];
#pragma unroll
            for (int i = 0; i < TM; i++)
#pragma unroll
                for (int jp = 0; jp < TN / 2; jp++)
                    acc[i][jp] = ffma2(a2[i], b2[jp], acc[i][jp]);
        }
        if (t + 1 < nk) sstore(cur ^ 1);
        __syncthreads();
    }

    // ---------------- epilogue ----------------
#pragma unroll
    for (int i = 0; i < TM; i++) {
        const int m = m0 + ty * TM + i;
        const float sc = scale[m], bb = bias[m];
#pragma unroll
        for (int jp = 0; jp < TN / 2; jp++) {
            float2 v = unpack2(acc[i][jp]);
#pragma unroll
            for (int half = 0; half < 2; half++) {
                const int n = n0 + tx * TN + 2 * jp + half;
                const float raw = half ? v.y : v.x;
                float val = raw * sc + bb;
                if constexpr (MODE == M_PIX1) {
                    g_pixel_space[((size_t)bz * 256 + m) * HW + n] = gelu_f(val);
                } else if constexpr (MODE == M_PKV) {
                    if (m < 128) {  // pixel_k : channel = h*16+d
                        g_kbuf[((size_t)(bz * NH + (m >> 4)) * DK + (m & 15)) * MT + LQ + n] = val;
                    } else {        // pixel_v
                        int mm = m - 128;
                        g_vbuf[((size_t)(bz * NH + (mm >> 5)) * DV + (mm & 31)) * MT + LQ + n] = val;
                    }
                } else if constexpr (MODE == M_Q1) {
                    g_qs[(size_t)m * NQ + n] = gelu_f(val);
                } else if constexpr (MODE == M_QKV) {
                    const int b = n >> 7, l = n & 127;
                    if (m < 128) {
                        g_qbuf[((size_t)(b * NH + (m >> 4)) * DK + (m & 15)) * LQ + l] = val;
                    } else if (m < 256) {
                        int mm = m - 128;
                        g_kbuf[((size_t)(b * NH + (mm >> 4)) * DK + (mm & 15)) * MT + l] = val;
                    } else {
                        int mm = m - 256;
                        g_vbuf[((size_t)(b * NH + (mm >> 5)) * DV + (mm & 31)) * MT + l] = val;
                    }
                } else if constexpr (MODE == M_C3) {
                    const int b = n >> 7, l = n & 127;
                    float r = extra[((size_t)b * CQ + m) * LQ + l];
                    g_qf[(size_t)m * NQ + n] = gelu_f(r + val);
                } else if constexpr (MODE == M_F1) {
                    g_ffn[(size_t)m * NQ + n] = gelu_f(val);
                } else {  // M_F2
                    const int b = n >> 7, l = n & 127;
                    float r = g_qf[(size_t)m * NQ + n];
                    C[((size_t)b * CQ + m) * LQ + l] = gelu_f(r + val);
                }
            }
        }
    }
}

// ---------------------------------------------------------------------------
// Attention: grid (bh=64, ms=4), 256 threads: l = tid&127, g = tid>>7 (2-way
// m interleave inside the block). Online softmax per thread, in-block 2-way
// merge, partials to global; combine kernel merges the 4 ms splits.
// ---------------------------------------------------------------------------
__global__ void __launch_bounds__(256)
attn_kernel(const float* __restrict__ s_sim, const float* __restrict__ b_sim)
{
    const int bh = blockIdx.x;           // b*8 + h
    const int ms = blockIdx.y;
    const int h  = bh & 7;
    const int tid = threadIdx.x;
    const int l = tid & 127;
    const int g = tid >> 7;

    __shared__ float ks[32][18];         // [mm][d]  (DK=16, padded)
    __shared__ float vs[32][34];         // [mm][d]  (DV=32, padded)
    __shared__ float S_mx[128], S_sum[128];
    __shared__ float S_acc[32][129];     // [d][l]

    const float ssim = s_sim[h], bsim = b_sim[h];

    u64 q2[8];
#pragma unroll
    for (int e = 0; e < 8; e++) {
        float qa = g_qbuf[((size_t)bh * DK + 2 * e) * LQ + l];
        float qb = g_qbuf[((size_t)bh * DK + 2 * e + 1) * LQ + l];
        q2[e] = pack2(qa, qb);
    }

    float mx = -1e30f, sum = 0.0f;
    u64 acc2[16];
#pragma unroll
    for (int p = 0; p < 16; p++) acc2[p] = 0ull;

    const int mbase = ms * MSLAB;
    for (int tt = 0; tt < MSLAB / 32; tt++) {
        const int m0 = mbase + tt * 32;
        // cooperative tile load (transposed into smem)
#pragma unroll
        for (int r = 0; r < 2; r++) {
            int e = r * 256 + tid;
            int d = e >> 5, mm = e & 31;
            ks[mm][d] = g_kbuf[((size_t)bh * DK + d) * MT + m0 + mm];
        }
#pragma unroll
        for (int r = 0; r < 4; r++) {
            int e = r * 256 + tid;
            int d = e >> 5, mm = e & 31;
            vs[mm][d] = g_vbuf[((size_t)bh * DV + d) * MT + m0 + mm];
        }
        __syncthreads();

        for (int mm = g; mm < 32; mm += 2) {
            u64 dacc = 0ull;
#pragma unroll
            for (int e = 0; e < 8; e++)
                dacc = ffma2(q2[e], *(const u64*)&ks[mm][2 * e], dacc);
            float2 dv = unpack2(dacc);
            float s = (dv.x + dv.y) * ssim + bsim;
            if (s > mx) {
                float corr = __expf(mx - s);
                sum *= corr;
                u64 c2 = pack2(corr, corr);
#pragma unroll
                for (int p = 0; p < 16; p++) acc2[p] = fmul2(acc2[p], c2);
                mx = s;
            }
            float pe = __expf(s - mx);
            sum += pe;
            u64 p2 = pack2(pe, pe);
#pragma unroll
            for (int p = 0; p < 16; p++)
                acc2[p] = ffma2(p2, *(const u64*)&vs[mm][2 * p], acc2[p]);
        }
        __syncthreads();
    }

    // in-block merge: g0 publishes, g1 merges + writes partials
    if (g == 0) {
        S_mx[l] = mx; S_sum[l] = sum;
#pragma unroll
        for (int p = 0; p < 16; p++) {
            float2 t = unpack2(acc2[p]);
            S_acc[2 * p][l] = t.x;
            S_acc[2 * p + 1][l] = t.y;
        }
    }
    __syncthreads();
    if (g == 1) {
        float omx = S_mx[l], osum = S_sum[l];
        float M  = fmaxf(omx, mx);
        float c0 = __expf(omx - M), c1 = __expf(mx - M);
        float tot = osum * c0 + sum * c1;
        const int base = (bh * MSPLIT + ms) * LQ + l;
        g_part_mx[base] = M;
        g_part_sum[base] = tot;
#pragma unroll
        for (int p = 0; p < 16; p++) {
            float2 t = unpack2(acc2[p]);
            g_part_acc[((size_t)(bh * MSPLIT + ms) * DV + 2 * p) * LQ + l]     = S_acc[2 * p][l] * c0 + t.x * c1;
            g_part_acc[((size_t)(bh * MSPLIT + ms) * DV + 2 * p + 1) * LQ + l] = S_acc[2 * p + 1][l] * c0 + t.y * c1;
        }
    }
}

__global__ void __launch_bounds__(128)
attn_combine(const float* __restrict__ s_ret, const float* __restrict__ b_ret)
{
    const int bh = blockIdx.x;
    const int b = bh >> 3, h = bh & 7;
    const int l = threadIdx.x;

    float M = -1e30f;
#pragma unroll
    for (int ms = 0; ms < MSPLIT; ms++)
        M = fmaxf(M, g_part_mx[(bh * MSPLIT + ms) * LQ + l]);
    float e[MSPLIT];
    float tot = 0.0f;
#pragma unroll
    for (int ms = 0; ms < MSPLIT; ms++) {
        e[ms] = __expf(g_part_mx[(bh * MSPLIT + ms) * LQ + l] - M);
        tot += g_part_sum[(bh * MSPLIT + ms) * LQ + l] * e[ms];
    }
    const float inv = 1.0f / tot;
#pragma unroll
    for (int d = 0; d < DV; d++) {
        float a = 0.0f;
#pragma unroll
        for (int ms = 0; ms < MSPLIT; ms++)
            a += g_part_acc[((size_t)(bh * MSPLIT + ms) * DV + d) * LQ + l] * e[ms];
        a *= inv;
        const int c = h * DV + d;
        a = gelu_f(a * s_ret[c] + b_ret[c]);
        g_ret[(size_t)c * NQ + b * LQ + l] = a;
    }
}

// ---------------------------------------------------------------------------
// Launch
// ---------------------------------------------------------------------------
extern "C" void kernel_launch(void* const* d_in, const int* in_sizes, int n_in,
                              void* d_out, int out_size)
{
    const float* pixel  = (const float*)d_in[0];
    const float* query  = (const float*)d_in[1];
    const float* w_q1   = (const float*)d_in[2];
    const float* s_q1   = (const float*)d_in[3];
    const float* b_q1   = (const float*)d_in[4];
    const float* w_p1   = (const float*)d_in[5];
    const float* s_p1   = (const float*)d_in[6];
    const float* b_p1   = (const float*)d_in[7];
    const float* w_qkv  = (const float*)d_in[8];
    const float* s_qkv  = (const float*)d_in[9];
    const float* b_qkv  = (const float*)d_in[10];
    const float* w_pkv  = (const float*)d_in[11];
    const float* s_pkv  = (const float*)d_in[12];
    const float* b_pkv  = (const float*)d_in[13];
    const float* s_sim  = (const float*)d_in[14];
    const float* b_sim  = (const float*)d_in[15];
    const float* s_ret  = (const float*)d_in[16];
    const float* b_ret  = (const float*)d_in[17];
    const float* w_c3   = (const float*)d_in[18];
    const float* s_c3   = (const float*)d_in[19];
    const float* b_c3   = (const float*)d_in[20];
    const float* w_f1   = (const float*)d_in[21];
    const float* s_f1   = (const float*)d_in[22];
    const float* b_f1   = (const float*)d_in[23];
    const float* w_f2   = (const float*)d_in[24];
    const float* s_f2   = (const float*)d_in[25];
    const float* b_f2   = (const float*)d_in[26];
    float* out = (float*)d_out;

    // 1) pixel bottleneck: gelu(bn(w_p1 @ gelu(pixel)))
    gemm_k<128, 128, 16, 8, 8, M_PIX1><<<dim3(2, 32, 8), 256>>>(
        w_p1, pixel, s_p1, b_p1, nullptr, nullptr, CP);
    // 2) pixel_kv -> scatter into K/V (m >= 128)
    gemm_k<128, 128, 16, 8, 8, M_PKV><<<dim3(3, 32, 8), 256>>>(
        w_pkv, nullptr, s_pkv, b_pkv, nullptr, nullptr, 256);
    // 3) query_space = gelu(bn(w_q1 @ query))
    gemm_k<128, 128, 16, 8, 8, M_Q1><<<dim3(2, 8, 1), 256>>>(
        w_q1, query, s_q1, b_q1, nullptr, nullptr, 256);
    // 4) query_qkv -> scatter q / k(m<128) / v(m<128)   [M=512 -> 4 m-blocks]
    gemm_k<128, 128, 16, 8, 8, M_QKV><<<dim3(4, 8, 1), 256>>>(
        w_qkv, nullptr, s_qkv, b_qkv, nullptr, nullptr, 256);
    // 5) attention (flash-style, 4-way m split) + 6) combine (+bn+gelu)
    attn_kernel<<<dim3(64, MSPLIT), 256>>>(s_sim, b_sim);
    attn_combine<<<64, 128>>>(s_ret, b_ret);
    // 7) out proj + residual: qf = gelu(query + bn(w_c3 @ ret))
    gemm_k<128, 128, 16, 8, 8, M_C3><<<dim3(2, 8, 1), 256>>>(
        w_c3, nullptr, s_c3, b_c3, query, nullptr, 256);
    // 8) ffn1 = gelu(bn(w_f1 @ qf))
    gemm_k<128, 128, 16, 8, 8, M_F1><<<dim3(16, 8, 1), 256>>>(
        w_f1, nullptr, s_f1, b_f1, nullptr, nullptr, 256);
    // 9) out = gelu(qf + bn(w_f2 @ ffn))   (smaller tiles: more blocks)
    gemm_k<64, 64, 16, 4, 4, M_F2><<<dim3(4, 16, 1), 256>>>(
        w_f2, nullptr, s_f2, b_f2, nullptr, out, 2048);
}